// round 8
// baseline (speedup 1.0000x reference)
#include <cuda_runtime.h>
#include <cuda_bf16.h>
#include <cstdint>

#define BB 16
#define CC 256
#define TT 1024

// Precomputed table (device global: no allocation allowed)
__device__ float g_M[256][9][256];    // [j][t][c]

// ---------------------------------------------------------------------------
// prep v3: 32 blocks x 256 threads. thread = channel c; w-slices live in
// REGISTERS across an 8-j loop (kills the redundant-LDG problem).
// M[j][t][c] = og[j,c] * sum_d fw[j,c,d] * kp[c,d,t]
// ---------------------------------------------------------------------------
__global__ void __launch_bounds__(256, 1)
prep_kernel(const float* __restrict__ w3, const float* __restrict__ w5,
            const float* __restrict__ w9, const float* __restrict__ og,
            const float* __restrict__ fw) {
    const int c = threadIdx.x;
    float a3[18], a5[30], a9[54];
    {
        const float2* p = reinterpret_cast<const float2*>(w3 + c * 18);
        #pragma unroll
        for (int i = 0; i < 9; i++)  { float2 v = p[i]; a3[2*i] = v.x; a3[2*i+1] = v.y; }
    }
    {
        const float2* p = reinterpret_cast<const float2*>(w5 + c * 30);
        #pragma unroll
        for (int i = 0; i < 15; i++) { float2 v = p[i]; a5[2*i] = v.x; a5[2*i+1] = v.y; }
    }
    {
        const float2* p = reinterpret_cast<const float2*>(w9 + c * 54);
        #pragma unroll
        for (int i = 0; i < 27; i++) { float2 v = p[i]; a9[2*i] = v.x; a9[2*i+1] = v.y; }
    }

    const int j0 = blockIdx.x * 8;
    #pragma unroll 1
    for (int jj = 0; jj < 8; jj++) {
        const int j = j0 + jj;
        float f[18];
        {
            const float2* p = reinterpret_cast<const float2*>(fw + ((size_t)j * 256 + c) * 18);
            #pragma unroll
            for (int i = 0; i < 9; i++) { float2 v = p[i]; f[2*i] = v.x; f[2*i+1] = v.y; }
        }
        const float g = og[(size_t)j * 256 + c];
        float s[9];
        #pragma unroll
        for (int t = 0; t < 9; t++) s[t] = 0.f;
        #pragma unroll
        for (int d = 0; d < 6; d++)
            #pragma unroll
            for (int t = 0; t < 3; t++) s[t] = fmaf(f[d], a3[d*3+t], s[t]);
        #pragma unroll
        for (int d = 0; d < 6; d++)
            #pragma unroll
            for (int t = 0; t < 5; t++) s[t] = fmaf(f[6+d], a5[d*5+t], s[t]);
        #pragma unroll
        for (int d = 0; d < 6; d++)
            #pragma unroll
            for (int t = 0; t < 9; t++) s[t] = fmaf(f[12+d], a9[d*9+t], s[t]);
        #pragma unroll
        for (int t = 0; t < 9; t++) g_M[j][t][c] = g * s[t];
    }
}

// ---------------------------------------------------------------------------
// LIF kernel: fused drive conv + latency scan + x passthrough.
// One warp per (b,c) row; 8 rows/block; conflict-free stride-33 smem.
// ---------------------------------------------------------------------------
__global__ void __launch_bounds__(256)
lif_kernel(const float* __restrict__ x,
           const float* __restrict__ w3, const float* __restrict__ b3,
           const float* __restrict__ w5, const float* __restrict__ b5,
           const float* __restrict__ w9, const float* __restrict__ b9,
           const float* __restrict__ rw, const float* __restrict__ rb,
           const float* __restrict__ ls,
           float* __restrict__ out_x, float* __restrict__ out_lat,
           float* __restrict__ out_act) {
    __shared__ float smem[8 * 33 * 32];
    const int warp = threadIdx.x >> 5, lane = threadIdx.x & 31;
    const int row = blockIdx.x * 8 + warp;          // b*256+c
    const int c = row & 255;
    const float* xr = x + (size_t)row * TT;
    float* xo = out_x + (size_t)row * TT;
    float* sp = smem + warp * (33 * 32);

    // stage x: coalesced LDG.128, fused passthrough STG.128, conflict-free STS
    #pragma unroll
    for (int i = 0; i < 8; i++) {
        const int p = i * 128 + lane * 4;
        float4 v = *(const float4*)(xr + p);
        *(float4*)(xo + p) = v;
        const int base = 33 * (p >> 5) + (p & 31);
        sp[base + 0] = v.x; sp[base + 1] = v.y; sp[base + 2] = v.z; sp[base + 3] = v.w;
    }

    // ---- per-warp effective 9-tap kernel ----
    float ew[9];
    #pragma unroll
    for (int i = 0; i < 9; i++) ew[i] = 0.f;
    float eb = 0.f;
    {
        const int d = lane;
        if (d < 6) {
            float r = rw[c * 18 + d];
            eb = r * b3[c * 6 + d];
            #pragma unroll
            for (int i = 0; i < 3; i++) ew[i + 3] = r * w3[(c * 6 + d) * 3 + i];
        } else if (d < 12) {
            int dd = d - 6;
            float r = rw[c * 18 + d];
            eb = r * b5[c * 6 + dd];
            #pragma unroll
            for (int i = 0; i < 5; i++) ew[i + 2] = r * w5[(c * 6 + dd) * 5 + i];
        } else if (d < 18) {
            int dd = d - 12;
            float r = rw[c * 18 + d];
            eb = r * b9[c * 6 + dd];
            #pragma unroll
            for (int i = 0; i < 9; i++) ew[i] = r * w9[(c * 6 + dd) * 9 + i];
        } else if (d == 31) {
            eb = rb[c];
        }
    }
    #pragma unroll
    for (int off = 16; off; off >>= 1) {
        #pragma unroll
        for (int i = 0; i < 9; i++) ew[i] += __shfl_xor_sync(0xffffffffu, ew[i], off);
        eb += __shfl_xor_sync(0xffffffffu, eb, off);
    }
    __syncwarp();

    const float AL  = (float)0.81873075307798185567;   // exp(-1/5)
    const float OM  = (float)0.18126924692201814433;   // 1 - alpha
    const float A32 = (float)0.00166155727317393354;   // alpha^32

    const int sb = 33 * lane;
    float dloc[32];

    {   // outputs 0..7
        float w[16];
        #pragma unroll
        for (int q = 0; q < 4; q++)  w[q] = (lane > 0) ? sp[sb - 5 + q] : 0.f;
        #pragma unroll
        for (int q = 4; q < 16; q++) w[q] = sp[sb + q - 4];
        #pragma unroll
        for (int k = 0; k < 8; k++) {
            float d = eb;
            #pragma unroll
            for (int i = 0; i < 9; i++) d = fmaf(ew[i], w[k + i], d);
            dloc[k] = d;
        }
    }
    {   // outputs 8..15
        float w[16];
        #pragma unroll
        for (int q = 0; q < 16; q++) w[q] = sp[sb + 4 + q];
        #pragma unroll
        for (int k = 0; k < 8; k++) {
            float d = eb;
            #pragma unroll
            for (int i = 0; i < 9; i++) d = fmaf(ew[i], w[k + i], d);
            dloc[8 + k] = d;
        }
    }
    {   // outputs 16..23
        float w[16];
        #pragma unroll
        for (int q = 0; q < 16; q++) w[q] = sp[sb + 12 + q];
        #pragma unroll
        for (int k = 0; k < 8; k++) {
            float d = eb;
            #pragma unroll
            for (int i = 0; i < 9; i++) d = fmaf(ew[i], w[k + i], d);
            dloc[16 + k] = d;
        }
    }
    {   // outputs 24..31
        float w[16];
        #pragma unroll
        for (int q = 0; q < 12; q++)  w[q] = sp[sb + 20 + q];
        #pragma unroll
        for (int q = 12; q < 16; q++) w[q] = (lane < 31) ? sp[sb + 21 + q] : 0.f;
        #pragma unroll
        for (int k = 0; k < 8; k++) {
            float d = eb;
            #pragma unroll
            for (int i = 0; i < 9; i++) d = fmaf(ew[i], w[k + i], d);
            dloc[24 + k] = d;
        }
    }

    // pass 1: local segment value from V=0
    float U = 0.f, A = A32;
    #pragma unroll
    for (int ss = 0; ss < 32; ss++) U = fmaf(AL, U, OM * dloc[ss]);

    // Kogge-Stone scan over (A,U)
    #pragma unroll
    for (int off = 1; off < 32; off <<= 1) {
        float Au = __shfl_up_sync(0xffffffffu, A, off);
        float Uu = __shfl_up_sync(0xffffffffu, U, off);
        if (lane >= off) { U = fmaf(A, Uu, U); A *= Au; }
    }
    float Vin = __shfl_up_sync(0xffffffffu, U, 1);
    if (lane == 0) Vin = 0.f;

    // pass 2: exact-order replay, first crossing
    float V = Vin;
    int lat = TT;
    const int t0 = lane * 32;
    #pragma unroll
    for (int ss = 0; ss < 32; ss++) {
        V = fmaf(AL, V, OM * dloc[ss]);
        if (lat == TT && V >= 0.01f) lat = t0 + ss;
    }
    #pragma unroll
    for (int off = 16; off; off >>= 1) lat = min(lat, __shfl_xor_sync(0xffffffffu, lat, off));

    if (lane == 0) {
        float latf = (float)lat;
        float sc = fmaxf(ls[0], 0.001f);
        out_lat[row] = latf;
        out_act[row] = expf(-latf / sc);
    }
}

// ---------------------------------------------------------------------------
// recon: TWO warps per (b,j) row (t-split) -> 8192 warps.
//   half 0: t=0..4  -> writes floats 0..4
//   half 1: t=5..8  -> writes floats 5..8, zeros 9..15, zeros [16,1024)
// All M/act loads are LDG.128. grid 1024 x 256 (4 rows/block).
// ---------------------------------------------------------------------------
__global__ void __launch_bounds__(256)
recon_kernel(const float* __restrict__ act, float* __restrict__ recon) {
    const int warp = threadIdx.x >> 5, lane = threadIdx.x & 31;
    const int r = blockIdx.x * 4 + (warp >> 1);
    const int half = warp & 1;
    const int b = r >> 8, j = r & 255;
    float* out = recon + (size_t)r * TT;           // r == b*256+j

    if (half) {
        // zero tail first (independent of act/M -> overlaps the loads below)
        const float4 z = make_float4(0.f, 0.f, 0.f, 0.f);
        float4* zp = (float4*)(out + 16);
        #pragma unroll
        for (int i = 0; i < 8; i++) {
            int idx = i * 32 + lane;
            if (idx < 252) zp[idx] = z;
        }
        if (lane >= 9 && lane < 16) out[lane] = 0.f;
    }

    const float4* ap = reinterpret_cast<const float4*>(act + b * 256 + lane * 8);
    const float4 a0 = ap[0], a1 = ap[1];

    if (half == 0) {
        float sums[5];
        #pragma unroll
        for (int t = 0; t < 5; t++) {
            const float4* mp = reinterpret_cast<const float4*>(&g_M[j][t][lane * 8]);
            const float4 m0 = mp[0], m1 = mp[1];
            float s0 = m0.x * a0.x, s1 = m0.y * a0.y, s2 = m0.z * a0.z, s3 = m0.w * a0.w;
            s0 = fmaf(m1.x, a1.x, s0); s1 = fmaf(m1.y, a1.y, s1);
            s2 = fmaf(m1.z, a1.z, s2); s3 = fmaf(m1.w, a1.w, s3);
            sums[t] = (s0 + s1) + (s2 + s3);
        }
        #pragma unroll
        for (int t = 0; t < 5; t++) {
            #pragma unroll
            for (int off = 16; off; off >>= 1)
                sums[t] += __shfl_xor_sync(0xffffffffu, sums[t], off);
        }
        if (lane == 0)      out[0] = sums[0];
        else if (lane == 1) out[1] = sums[1];
        else if (lane == 2) out[2] = sums[2];
        else if (lane == 3) out[3] = sums[3];
        else if (lane == 4) out[4] = sums[4];
    } else {
        float sums[4];
        #pragma unroll
        for (int t = 0; t < 4; t++) {
            const float4* mp = reinterpret_cast<const float4*>(&g_M[j][t + 5][lane * 8]);
            const float4 m0 = mp[0], m1 = mp[1];
            float s0 = m0.x * a0.x, s1 = m0.y * a0.y, s2 = m0.z * a0.z, s3 = m0.w * a0.w;
            s0 = fmaf(m1.x, a1.x, s0); s1 = fmaf(m1.y, a1.y, s1);
            s2 = fmaf(m1.z, a1.z, s2); s3 = fmaf(m1.w, a1.w, s3);
            sums[t] = (s0 + s1) + (s2 + s3);
        }
        #pragma unroll
        for (int t = 0; t < 4; t++) {
            #pragma unroll
            for (int off = 16; off; off >>= 1)
                sums[t] += __shfl_xor_sync(0xffffffffu, sums[t], off);
        }
        if (lane == 5)      out[5] = sums[0];
        else if (lane == 6) out[6] = sums[1];
        else if (lane == 7) out[7] = sums[2];
        else if (lane == 8) out[8] = sums[3];
    }
}

// ---------------------------------------------------------------------------
extern "C" void kernel_launch(void* const* d_in, const int* in_sizes, int n_in,
                              void* d_out, int out_size) {
    const float* x  = (const float*)d_in[0];
    const float* w3 = (const float*)d_in[1];
    const float* b3 = (const float*)d_in[2];
    const float* w5 = (const float*)d_in[3];
    const float* b5 = (const float*)d_in[4];
    const float* w9 = (const float*)d_in[5];
    const float* b9 = (const float*)d_in[6];
    const float* rw = (const float*)d_in[7];
    const float* rb = (const float*)d_in[8];
    const float* ls = (const float*)d_in[9];
    const float* og = (const float*)d_in[10];
    const float* fw = (const float*)d_in[11];

    float* out      = (float*)d_out;
    float* recon    = out;                         // (B,C,T)  4194304
    float* out_x    = out + 4194304;               // (B,C,T)  4194304
    float* out_lat  = out + 8388608;               // (B,C)       4096
    float* out_act  = out + 8392704;               // (B,C)       4096

    prep_kernel<<<32, 256>>>(w3, w5, w9, og, fw);
    lif_kernel<<<512, 256>>>(x, w3, b3, w5, b5, w9, b9, rw, rb, ls,
                             out_x, out_lat, out_act);
    recon_kernel<<<1024, 256>>>(out_act, recon);
}

// round 10
// speedup vs baseline: 1.0502x; 1.0502x over previous
#include <cuda_runtime.h>
#include <cuda_bf16.h>
#include <cstdint>

#define BB 16
#define CC 256
#define TT 1024

// Precomputed table + sync counters (device globals: no allocation allowed)
__device__ float g_M[256][9][256];    // [j][t][c]
__device__ int g_actdone[16];         // lif blocks done per batch (target 32)
__device__ int g_prepdone;            // prep blocks done (target 512)
__device__ int g_headsdone;           // heads blocks done (target 256, then reset all)

#define LIF_BLOCKS 512
#define PREP_BASE  512
#define ZF_BASE    1024
#define HEADS_BASE 3072
#define HEADS_BLOCKS 256
#define TOTAL_BLOCKS (HEADS_BASE + HEADS_BLOCKS)

__global__ void __launch_bounds__(256)
mega_kernel(const float* __restrict__ x,
            const float* __restrict__ w3, const float* __restrict__ b3,
            const float* __restrict__ w5, const float* __restrict__ b5,
            const float* __restrict__ w9, const float* __restrict__ b9,
            const float* __restrict__ rw, const float* __restrict__ rb,
            const float* __restrict__ ls,
            const float* __restrict__ og, const float* __restrict__ fw,
            float* __restrict__ out_x, float* __restrict__ out_lat,
            float* __restrict__ out_act, float* __restrict__ recon) {
    __shared__ float smem[8 * 33 * 32];                 // 33792 B, reused by roles
    const int bid = blockIdx.x;
    const int tid = threadIdx.x;

    if (bid >= ZF_BASE && bid < HEADS_BASE) {
        // =================== tail zero-fill role ===================
        // zero floats [16,1024) of 2 rows = 252 float4 each (heads own [0,16))
        const int r0 = (bid - ZF_BASE) * 2;
        const float4 z = make_float4(0.f, 0.f, 0.f, 0.f);
        #pragma unroll
        for (int rr = 0; rr < 2; rr++) {
            float4* zp = (float4*)(recon + (size_t)(r0 + rr) * TT + 16);
            if (tid < 252) zp[tid] = z;
        }
        return;
    }

    if (bid < LIF_BLOCKS) {
        // =================== LIF role ===================
        const int warp = tid >> 5, lane = tid & 31;
        const int row = bid * 8 + warp;              // b*256+c
        const int c = row & 255;
        const float* xr = x + (size_t)row * TT;
        float* xo = out_x + (size_t)row * TT;
        float* sp = smem + warp * (33 * 32);

        #pragma unroll
        for (int i = 0; i < 8; i++) {
            const int p = i * 128 + lane * 4;
            float4 v = *(const float4*)(xr + p);
            *(float4*)(xo + p) = v;
            const int base = 33 * (p >> 5) + (p & 31);
            sp[base + 0] = v.x; sp[base + 1] = v.y; sp[base + 2] = v.z; sp[base + 3] = v.w;
        }

        // per-warp effective 9-tap kernel
        float ew[9];
        #pragma unroll
        for (int i = 0; i < 9; i++) ew[i] = 0.f;
        float eb = 0.f;
        {
            const int d = lane;
            if (d < 6) {
                float r = rw[c * 18 + d];
                eb = r * b3[c * 6 + d];
                #pragma unroll
                for (int i = 0; i < 3; i++) ew[i + 3] = r * w3[(c * 6 + d) * 3 + i];
            } else if (d < 12) {
                int dd = d - 6;
                float r = rw[c * 18 + d];
                eb = r * b5[c * 6 + dd];
                #pragma unroll
                for (int i = 0; i < 5; i++) ew[i + 2] = r * w5[(c * 6 + dd) * 5 + i];
            } else if (d < 18) {
                int dd = d - 12;
                float r = rw[c * 18 + d];
                eb = r * b9[c * 6 + dd];
                #pragma unroll
                for (int i = 0; i < 9; i++) ew[i] = r * w9[(c * 6 + dd) * 9 + i];
            } else if (d == 31) {
                eb = rb[c];
            }
        }
        #pragma unroll
        for (int off = 16; off; off >>= 1) {
            #pragma unroll
            for (int i = 0; i < 9; i++) ew[i] += __shfl_xor_sync(0xffffffffu, ew[i], off);
            eb += __shfl_xor_sync(0xffffffffu, eb, off);
        }
        __syncwarp();

        const float AL  = (float)0.81873075307798185567;   // exp(-1/5)
        const float OM  = (float)0.18126924692201814433;   // 1 - alpha
        const float A32 = (float)0.00166155727317393354;   // alpha^32

        const int sb = 33 * lane;
        float dloc[32];

        {   // outputs 0..7
            float w[16];
            #pragma unroll
            for (int q = 0; q < 4; q++)  w[q] = (lane > 0) ? sp[sb - 5 + q] : 0.f;
            #pragma unroll
            for (int q = 4; q < 16; q++) w[q] = sp[sb + q - 4];
            #pragma unroll
            for (int k = 0; k < 8; k++) {
                float d = eb;
                #pragma unroll
                for (int i = 0; i < 9; i++) d = fmaf(ew[i], w[k + i], d);
                dloc[k] = d;
            }
        }
        {   // outputs 8..15
            float w[16];
            #pragma unroll
            for (int q = 0; q < 16; q++) w[q] = sp[sb + 4 + q];
            #pragma unroll
            for (int k = 0; k < 8; k++) {
                float d = eb;
                #pragma unroll
                for (int i = 0; i < 9; i++) d = fmaf(ew[i], w[k + i], d);
                dloc[8 + k] = d;
            }
        }
        {   // outputs 16..23
            float w[16];
            #pragma unroll
            for (int q = 0; q < 16; q++) w[q] = sp[sb + 12 + q];
            #pragma unroll
            for (int k = 0; k < 8; k++) {
                float d = eb;
                #pragma unroll
                for (int i = 0; i < 9; i++) d = fmaf(ew[i], w[k + i], d);
                dloc[16 + k] = d;
            }
        }
        {   // outputs 24..31
            float w[16];
            #pragma unroll
            for (int q = 0; q < 12; q++)  w[q] = sp[sb + 20 + q];
            #pragma unroll
            for (int q = 12; q < 16; q++) w[q] = (lane < 31) ? sp[sb + 21 + q] : 0.f;
            #pragma unroll
            for (int k = 0; k < 8; k++) {
                float d = eb;
                #pragma unroll
                for (int i = 0; i < 9; i++) d = fmaf(ew[i], w[k + i], d);
                dloc[24 + k] = d;
            }
        }

        // pass 1: local segment value from V=0
        float U = 0.f, A = A32;
        #pragma unroll
        for (int ss = 0; ss < 32; ss++) U = fmaf(AL, U, OM * dloc[ss]);

        // Kogge-Stone scan over (A,U)
        #pragma unroll
        for (int off = 1; off < 32; off <<= 1) {
            float Au = __shfl_up_sync(0xffffffffu, A, off);
            float Uu = __shfl_up_sync(0xffffffffu, U, off);
            if (lane >= off) { U = fmaf(A, Uu, U); A *= Au; }
        }
        float Vin = __shfl_up_sync(0xffffffffu, U, 1);
        if (lane == 0) Vin = 0.f;

        // pass 2: exact-order replay, first crossing
        float V = Vin;
        int lat = TT;
        const int t0 = lane * 32;
        #pragma unroll
        for (int ss = 0; ss < 32; ss++) {
            V = fmaf(AL, V, OM * dloc[ss]);
            if (lat == TT && V >= 0.01f) lat = t0 + ss;
        }
        #pragma unroll
        for (int off = 16; off; off >>= 1) lat = min(lat, __shfl_xor_sync(0xffffffffu, lat, off));

        if (lane == 0) {
            float latf = (float)lat;
            float sc = fmaxf(ls[0], 0.001f);
            out_lat[row] = latf;
            out_act[row] = expf(-latf / sc);
        }
        // publish act for this block's batch
        __syncthreads();
        if (tid == 0) {
            __threadfence();
            atomicAdd(&g_actdone[bid >> 5], 1);
        }
        return;
    }

    if (bid < ZF_BASE) {
        // =================== M-prep role ===================
        const int m = bid - PREP_BASE;
        const int j = m >> 1;
        const int cbase = (m & 1) * 128;
        const int ci = tid & 127;
        const int c = cbase + ci;
        float* sA = smem;                               // [128][6] used

        if (tid < 128) {
            float f[12];
            {
                const float2* p = reinterpret_cast<const float2*>(fw + ((size_t)j * 256 + c) * 18);
                #pragma unroll
                for (int i = 0; i < 6; i++) { float2 v = p[i]; f[2*i] = v.x; f[2*i+1] = v.y; }
            }
            float s[5];
            #pragma unroll
            for (int t = 0; t < 5; t++) s[t] = 0.f;
            {
                float a[18];
                const float2* p = reinterpret_cast<const float2*>(w3 + c * 18);
                #pragma unroll
                for (int i = 0; i < 9; i++) { float2 v = p[i]; a[2*i] = v.x; a[2*i+1] = v.y; }
                #pragma unroll
                for (int d = 0; d < 6; d++)
                    #pragma unroll
                    for (int t = 0; t < 3; t++) s[t] = fmaf(f[d], a[d*3+t], s[t]);
            }
            {
                float a[30];
                const float2* p = reinterpret_cast<const float2*>(w5 + c * 30);
                #pragma unroll
                for (int i = 0; i < 15; i++) { float2 v = p[i]; a[2*i] = v.x; a[2*i+1] = v.y; }
                #pragma unroll
                for (int d = 0; d < 6; d++)
                    #pragma unroll
                    for (int t = 0; t < 5; t++) s[t] = fmaf(f[6+d], a[d*5+t], s[t]);
            }
            #pragma unroll
            for (int t = 0; t < 5; t++) sA[ci * 6 + t] = s[t];
            __syncthreads();
        } else {
            float f[6];
            {
                const float2* p = reinterpret_cast<const float2*>(fw + ((size_t)j * 256 + c) * 18 + 12);
                #pragma unroll
                for (int i = 0; i < 3; i++) { float2 v = p[i]; f[2*i] = v.x; f[2*i+1] = v.y; }
            }
            const float g = og[(size_t)j * 256 + c];
            float s[9];
            #pragma unroll
            for (int t = 0; t < 9; t++) s[t] = 0.f;
            {
                float a[54];
                const float2* p = reinterpret_cast<const float2*>(w9 + c * 54);
                #pragma unroll
                for (int i = 0; i < 27; i++) { float2 v = p[i]; a[2*i] = v.x; a[2*i+1] = v.y; }
                #pragma unroll
                for (int d = 0; d < 6; d++)
                    #pragma unroll
                    for (int t = 0; t < 9; t++) s[t] = fmaf(f[d], a[d*9+t], s[t]);
            }
            __syncthreads();
            #pragma unroll
            for (int t = 0; t < 5; t++) s[t] += sA[ci * 6 + t];
            #pragma unroll
            for (int t = 0; t < 9; t++) g_M[j][t][c] = g * s[t];
        }
        __syncthreads();
        if (tid == 0) {
            __threadfence();
            atomicAdd(&g_prepdone, 1);
        }
        return;
    }

    // =================== heads role ===================
    // 256 blocks x 8 warps = 2048 warps; warp w handles rows (b, j0) & (b, j0+1),
    // b = w>>7, j0 = (w&127)*2. Block spans a single b = (bid-HEADS_BASE)>>4.
    {
        const int hb = (bid - HEADS_BASE) >> 4;          // batch this block serves
        if (tid == 0) {
            while (atomicAdd(&g_prepdone, 0) < 512) __nanosleep(64);
            while (atomicAdd(&g_actdone[hb], 0) < 32) __nanosleep(64);
            __threadfence();
        }
        __syncthreads();

        const int warp = tid >> 5, lane = tid & 31;
        const int w = (bid - HEADS_BASE) * 8 + warp;     // 0..2047
        const int b = w >> 7;
        const int j0 = (w & 127) * 2;

        const float4* ap = reinterpret_cast<const float4*>(out_act + b * 256 + lane * 8);
        const float4 a0 = ap[0], a1 = ap[1];

        #pragma unroll
        for (int jj = 0; jj < 2; jj++) {
            const int j = j0 + jj;
            float sums[9];
            #pragma unroll
            for (int t = 0; t < 9; t++) {
                const float4* mp = reinterpret_cast<const float4*>(&g_M[j][t][lane * 8]);
                const float4 m0 = mp[0], m1 = mp[1];
                float s0 = m0.x * a0.x, s1 = m0.y * a0.y, s2 = m0.z * a0.z, s3 = m0.w * a0.w;
                s0 = fmaf(m1.x, a1.x, s0); s1 = fmaf(m1.y, a1.y, s1);
                s2 = fmaf(m1.z, a1.z, s2); s3 = fmaf(m1.w, a1.w, s3);
                sums[t] = (s0 + s1) + (s2 + s3);
            }
            #pragma unroll
            for (int t = 0; t < 9; t++) {
                #pragma unroll
                for (int off = 16; off; off >>= 1)
                    sums[t] += __shfl_xor_sync(0xffffffffu, sums[t], off);
            }
            float* out = recon + ((size_t)b * 256 + j) * TT;
            if (lane == 0)      *(float4*)(out + 0)  = make_float4(sums[0], sums[1], sums[2], sums[3]);
            else if (lane == 1) *(float4*)(out + 4)  = make_float4(sums[4], sums[5], sums[6], sums[7]);
            else if (lane == 2) *(float4*)(out + 8)  = make_float4(sums[8], 0.f, 0.f, 0.f);
            else if (lane == 3) *(float4*)(out + 12) = make_float4(0.f, 0.f, 0.f, 0.f);
        }

        // epilogue: last heads block resets all counters (graph-replay safe)
        __syncthreads();
        if (tid == 0) {
            __threadfence();
            int v = atomicAdd(&g_headsdone, 1);
            if (v == HEADS_BLOCKS - 1) {
                #pragma unroll
                for (int i = 0; i < 16; i++) g_actdone[i] = 0;
                g_prepdone = 0;
                g_headsdone = 0;
                __threadfence();
            }
        }
    }
}

// ---------------------------------------------------------------------------
extern "C" void kernel_launch(void* const* d_in, const int* in_sizes, int n_in,
                              void* d_out, int out_size) {
    const float* x  = (const float*)d_in[0];
    const float* w3 = (const float*)d_in[1];
    const float* b3 = (const float*)d_in[2];
    const float* w5 = (const float*)d_in[3];
    const float* b5 = (const float*)d_in[4];
    const float* w9 = (const float*)d_in[5];
    const float* b9 = (const float*)d_in[6];
    const float* rw = (const float*)d_in[7];
    const float* rb = (const float*)d_in[8];
    const float* ls = (const float*)d_in[9];
    const float* og = (const float*)d_in[10];
    const float* fw = (const float*)d_in[11];

    float* out      = (float*)d_out;
    float* recon    = out;                         // (B,C,T)  4194304
    float* out_x    = out + 4194304;               // (B,C,T)  4194304
    float* out_lat  = out + 8388608;               // (B,C)       4096
    float* out_act  = out + 8392704;               // (B,C)       4096

    mega_kernel<<<TOTAL_BLOCKS, 256>>>(x, w3, b3, w5, b5, w9, b9, rw, rb, ls,
                                       og, fw, out_x, out_lat, out_act, recon);
}

// round 11
// speedup vs baseline: 1.3539x; 1.2892x over previous
#include <cuda_runtime.h>
#include <cuda_bf16.h>
#include <cstdint>

#define BB 16
#define CC 256
#define TT 1024

// Precomputed table (device global: no allocation allowed)
__device__ float g_M[256][9][256];    // [j][t][c]

#define LIF_BLOCKS 512
#define PREP_BASE  512
#define ZF_BASE    1024
#define ZF_BLOCKS  2048
#define TOTAL_BLOCKS (ZF_BASE + ZF_BLOCKS)

// ---------------------------------------------------------------------------
// Fused kernel:
//   blocks [0,512)      : LIF (8 rows each, effw computed in-warp)
//   blocks [512,1024)   : M[j][t][c-half] prep
//   blocks [1024,3072)  : zero-fill recon floats [9,1024) of 2 rows each
// ---------------------------------------------------------------------------
__global__ void __launch_bounds__(256)
fused_kernel(const float* __restrict__ x,
             const float* __restrict__ w3, const float* __restrict__ b3,
             const float* __restrict__ w5, const float* __restrict__ b5,
             const float* __restrict__ w9, const float* __restrict__ b9,
             const float* __restrict__ rw, const float* __restrict__ rb,
             const float* __restrict__ ls,
             const float* __restrict__ og, const float* __restrict__ fw,
             float* __restrict__ out_x, float* __restrict__ out_lat,
             float* __restrict__ out_act, float* __restrict__ recon) {
    __shared__ float smem[8 * 33 * 32];                 // 33792 B, reused by roles
    const int bid = blockIdx.x;
    const int tid = threadIdx.x;

    if (bid >= ZF_BASE) {
        // =================== zero-fill role: floats [9,1024) of 2 rows ======
        const int r0 = (bid - ZF_BASE) * 2;
        const float4 z = make_float4(0.f, 0.f, 0.f, 0.f);
        #pragma unroll
        for (int rr = 0; rr < 2; rr++) {
            float* row = recon + (size_t)(r0 + rr) * TT;
            if (tid < 3) row[9 + tid] = 0.f;             // floats 9,10,11
            float4* zp = (float4*)(row + 12);            // floats [12,1024) = 253 f4
            if (tid < 253) zp[tid] = z;
        }
        return;
    }

    if (bid < LIF_BLOCKS) {
        // =================== LIF role ===================
        const int warp = tid >> 5, lane = tid & 31;
        const int row = bid * 8 + warp;              // b*256+c
        const int c = row & 255;
        const float* xr = x + (size_t)row * TT;
        float* xo = out_x + (size_t)row * TT;
        float* sp = smem + warp * (33 * 32);

        #pragma unroll
        for (int i = 0; i < 8; i++) {
            const int p = i * 128 + lane * 4;
            float4 v = *(const float4*)(xr + p);
            *(float4*)(xo + p) = v;
            const int base = 33 * (p >> 5) + (p & 31);
            sp[base + 0] = v.x; sp[base + 1] = v.y; sp[base + 2] = v.z; sp[base + 3] = v.w;
        }

        // per-warp effective 9-tap kernel
        float ew[9];
        #pragma unroll
        for (int i = 0; i < 9; i++) ew[i] = 0.f;
        float eb = 0.f;
        {
            const int d = lane;
            if (d < 6) {
                float r = rw[c * 18 + d];
                eb = r * b3[c * 6 + d];
                #pragma unroll
                for (int i = 0; i < 3; i++) ew[i + 3] = r * w3[(c * 6 + d) * 3 + i];
            } else if (d < 12) {
                int dd = d - 6;
                float r = rw[c * 18 + d];
                eb = r * b5[c * 6 + dd];
                #pragma unroll
                for (int i = 0; i < 5; i++) ew[i + 2] = r * w5[(c * 6 + dd) * 5 + i];
            } else if (d < 18) {
                int dd = d - 12;
                float r = rw[c * 18 + d];
                eb = r * b9[c * 6 + dd];
                #pragma unroll
                for (int i = 0; i < 9; i++) ew[i] = r * w9[(c * 6 + dd) * 9 + i];
            } else if (d == 31) {
                eb = rb[c];
            }
        }
        #pragma unroll
        for (int off = 16; off; off >>= 1) {
            #pragma unroll
            for (int i = 0; i < 9; i++) ew[i] += __shfl_xor_sync(0xffffffffu, ew[i], off);
            eb += __shfl_xor_sync(0xffffffffu, eb, off);
        }
        __syncwarp();

        const float AL  = (float)0.81873075307798185567;   // exp(-1/5)
        const float OM  = (float)0.18126924692201814433;   // 1 - alpha
        const float A32 = (float)0.00166155727317393354;   // alpha^32

        const int sb = 33 * lane;
        float dloc[32];

        {   // outputs 0..7
            float w[16];
            #pragma unroll
            for (int q = 0; q < 4; q++)  w[q] = (lane > 0) ? sp[sb - 5 + q] : 0.f;
            #pragma unroll
            for (int q = 4; q < 16; q++) w[q] = sp[sb + q - 4];
            #pragma unroll
            for (int k = 0; k < 8; k++) {
                float d = eb;
                #pragma unroll
                for (int i = 0; i < 9; i++) d = fmaf(ew[i], w[k + i], d);
                dloc[k] = d;
            }
        }
        {   // outputs 8..15
            float w[16];
            #pragma unroll
            for (int q = 0; q < 16; q++) w[q] = sp[sb + 4 + q];
            #pragma unroll
            for (int k = 0; k < 8; k++) {
                float d = eb;
                #pragma unroll
                for (int i = 0; i < 9; i++) d = fmaf(ew[i], w[k + i], d);
                dloc[8 + k] = d;
            }
        }
        {   // outputs 16..23
            float w[16];
            #pragma unroll
            for (int q = 0; q < 16; q++) w[q] = sp[sb + 12 + q];
            #pragma unroll
            for (int k = 0; k < 8; k++) {
                float d = eb;
                #pragma unroll
                for (int i = 0; i < 9; i++) d = fmaf(ew[i], w[k + i], d);
                dloc[16 + k] = d;
            }
        }
        {   // outputs 24..31
            float w[16];
            #pragma unroll
            for (int q = 0; q < 12; q++)  w[q] = sp[sb + 20 + q];
            #pragma unroll
            for (int q = 12; q < 16; q++) w[q] = (lane < 31) ? sp[sb + 21 + q] : 0.f;
            #pragma unroll
            for (int k = 0; k < 8; k++) {
                float d = eb;
                #pragma unroll
                for (int i = 0; i < 9; i++) d = fmaf(ew[i], w[k + i], d);
                dloc[24 + k] = d;
            }
        }

        // pass 1: local segment value from V=0
        float U = 0.f, A = A32;
        #pragma unroll
        for (int ss = 0; ss < 32; ss++) U = fmaf(AL, U, OM * dloc[ss]);

        // Kogge-Stone scan over (A,U)
        #pragma unroll
        for (int off = 1; off < 32; off <<= 1) {
            float Au = __shfl_up_sync(0xffffffffu, A, off);
            float Uu = __shfl_up_sync(0xffffffffu, U, off);
            if (lane >= off) { U = fmaf(A, Uu, U); A *= Au; }
        }
        float Vin = __shfl_up_sync(0xffffffffu, U, 1);
        if (lane == 0) Vin = 0.f;

        // pass 2: exact-order replay, first crossing
        float V = Vin;
        int lat = TT;
        const int t0 = lane * 32;
        #pragma unroll
        for (int ss = 0; ss < 32; ss++) {
            V = fmaf(AL, V, OM * dloc[ss]);
            if (lat == TT && V >= 0.01f) lat = t0 + ss;
        }
        #pragma unroll
        for (int off = 16; off; off >>= 1) lat = min(lat, __shfl_xor_sync(0xffffffffu, lat, off));

        if (lane == 0) {
            float latf = (float)lat;
            float sc = fmaxf(ls[0], 0.001f);
            out_lat[row] = latf;
            out_act[row] = expf(-latf / sc);
        }
        return;
    }

    // =================== M-prep role ===================
    {
        const int m = bid - PREP_BASE;
        const int j = m >> 1;
        const int cbase = (m & 1) * 128;
        const int ci = tid & 127;
        const int c = cbase + ci;
        float* sA = smem;                               // [128][6] used

        if (tid < 128) {
            float f[12];
            {
                const float2* p = reinterpret_cast<const float2*>(fw + ((size_t)j * 256 + c) * 18);
                #pragma unroll
                for (int i = 0; i < 6; i++) { float2 v = p[i]; f[2*i] = v.x; f[2*i+1] = v.y; }
            }
            float s[5];
            #pragma unroll
            for (int t = 0; t < 5; t++) s[t] = 0.f;
            {
                float a[18];
                const float2* p = reinterpret_cast<const float2*>(w3 + c * 18);
                #pragma unroll
                for (int i = 0; i < 9; i++) { float2 v = p[i]; a[2*i] = v.x; a[2*i+1] = v.y; }
                #pragma unroll
                for (int d = 0; d < 6; d++)
                    #pragma unroll
                    for (int t = 0; t < 3; t++) s[t] = fmaf(f[d], a[d*3+t], s[t]);
            }
            {
                float a[30];
                const float2* p = reinterpret_cast<const float2*>(w5 + c * 30);
                #pragma unroll
                for (int i = 0; i < 15; i++) { float2 v = p[i]; a[2*i] = v.x; a[2*i+1] = v.y; }
                #pragma unroll
                for (int d = 0; d < 6; d++)
                    #pragma unroll
                    for (int t = 0; t < 5; t++) s[t] = fmaf(f[6+d], a[d*5+t], s[t]);
            }
            #pragma unroll
            for (int t = 0; t < 5; t++) sA[ci * 6 + t] = s[t];
            __syncthreads();
        } else {
            float f[6];
            {
                const float2* p = reinterpret_cast<const float2*>(fw + ((size_t)j * 256 + c) * 18 + 12);
                #pragma unroll
                for (int i = 0; i < 3; i++) { float2 v = p[i]; f[2*i] = v.x; f[2*i+1] = v.y; }
            }
            const float g = og[(size_t)j * 256 + c];
            float s[9];
            #pragma unroll
            for (int t = 0; t < 9; t++) s[t] = 0.f;
            {
                float a[54];
                const float2* p = reinterpret_cast<const float2*>(w9 + c * 54);
                #pragma unroll
                for (int i = 0; i < 27; i++) { float2 v = p[i]; a[2*i] = v.x; a[2*i+1] = v.y; }
                #pragma unroll
                for (int d = 0; d < 6; d++)
                    #pragma unroll
                    for (int t = 0; t < 9; t++) s[t] = fmaf(f[d], a[d*9+t], s[t]);
            }
            __syncthreads();
            #pragma unroll
            for (int t = 0; t < 5; t++) s[t] += sA[ci * 6 + t];
            #pragma unroll
            for (int t = 0; t < 9; t++) g_M[j][t][c] = g * s[t];
        }
    }
}

// ---------------------------------------------------------------------------
// heads: warp per (j,t). 256 blocks x 9 warps (288 thr); j = bid, t = warp.
// M row read once chip-wide (2 LDG.128/warp); act (16KB) L1-hot; 16 per-b
// accumulators -> butterfly reduce -> lane b stores recon[b,j,t] (t<9).
// ---------------------------------------------------------------------------
__global__ void __launch_bounds__(288)
heads_kernel(const float* __restrict__ act, float* __restrict__ recon) {
    const int j = blockIdx.x;
    const int t = threadIdx.x / 32;
    const int lane = threadIdx.x & 31;

    const float4* mp = reinterpret_cast<const float4*>(&g_M[j][t][lane * 8]);
    const float4 m0 = mp[0], m1 = mp[1];

    float sums[16];
    #pragma unroll
    for (int b = 0; b < 16; b++) {
        const float4* ap = reinterpret_cast<const float4*>(act + b * 256 + lane * 8);
        const float4 a0 = ap[0], a1 = ap[1];
        float s0 = m0.x * a0.x, s1 = m0.y * a0.y, s2 = m0.z * a0.z, s3 = m0.w * a0.w;
        s0 = fmaf(m1.x, a1.x, s0); s1 = fmaf(m1.y, a1.y, s1);
        s2 = fmaf(m1.z, a1.z, s2); s3 = fmaf(m1.w, a1.w, s3);
        sums[b] = (s0 + s1) + (s2 + s3);
    }
    #pragma unroll
    for (int b = 0; b < 16; b++) {
        #pragma unroll
        for (int off = 16; off; off >>= 1)
            sums[b] += __shfl_xor_sync(0xffffffffu, sums[b], off);
    }

    if (lane < 16) {
        float v = sums[0];
        #pragma unroll
        for (int b = 1; b < 16; b++) if (lane == b) v = sums[b];
        recon[((size_t)lane * 256 + j) * TT + t] = v;
    }
}

// ---------------------------------------------------------------------------
extern "C" void kernel_launch(void* const* d_in, const int* in_sizes, int n_in,
                              void* d_out, int out_size) {
    const float* x  = (const float*)d_in[0];
    const float* w3 = (const float*)d_in[1];
    const float* b3 = (const float*)d_in[2];
    const float* w5 = (const float*)d_in[3];
    const float* b5 = (const float*)d_in[4];
    const float* w9 = (const float*)d_in[5];
    const float* b9 = (const float*)d_in[6];
    const float* rw = (const float*)d_in[7];
    const float* rb = (const float*)d_in[8];
    const float* ls = (const float*)d_in[9];
    const float* og = (const float*)d_in[10];
    const float* fw = (const float*)d_in[11];

    float* out      = (float*)d_out;
    float* recon    = out;                         // (B,C,T)  4194304
    float* out_x    = out + 4194304;               // (B,C,T)  4194304
    float* out_lat  = out + 8388608;               // (B,C)       4096
    float* out_act  = out + 8392704;               // (B,C)       4096

    fused_kernel<<<TOTAL_BLOCKS, 256>>>(x, w3, b3, w5, b5, w9, b9, rw, rb, ls,
                                        og, fw, out_x, out_lat, out_act, recon);
    heads_kernel<<<256, 288>>>(out_act, recon);
}